// round 16
// baseline (speedup 1.0000x reference)
#include <cuda_runtime.h>
#include <cuda_bf16.h>
#include <stdint.h>

typedef unsigned long long ull;

#define N_ROWS 1024   // N
#define P_PIX  1024   // P
#define E_DIM  512    // ENC / TAG / LANG
#define A_DIM  256    // ATT

// fp32 scratch
__device__ float g_att1 [P_PIX * A_DIM];    // (P, A)  enc@We^T + be
__device__ float g_att23[N_ROWS * A_DIM];   // (N, A)  dh@Wt^T + bt
__device__ float g_att3 [N_ROWS * A_DIM];   // (N, A)  lo@Wl^T + bl
__device__ float g_att  [N_ROWS * P_PIX];   // (N, P)  = sum_a |x|*w/2 (shifted)
__device__ float g_c1   [P_PIX];            // c1[p] = 0.5*sum_a att1[p,a]*Wf[a]

// pre-split packed scratch: uint2 = {bf16x2 hi (k even,k odd), bf16x2 lo}
__device__ uint2 g_encA [P_PIX  * E_DIM / 2];   // [p][e/2]
__device__ uint2 g_dhA  [N_ROWS * E_DIM / 2];   // [n][e/2]
__device__ uint2 g_loA  [N_ROWS * E_DIM / 2];   // [n][e/2]
__device__ uint2 g_WeP  [A_DIM  * E_DIM / 2];   // [a][e/2]
__device__ uint2 g_WtP  [A_DIM  * E_DIM / 2];
__device__ uint2 g_WlP  [A_DIM  * E_DIM / 2];
__device__ uint2 g_encB [(P_PIX / 2) * E_DIM];  // [p/2][e]
__device__ uint2 g_alphaP[N_ROWS * P_PIX / 2];  // [n][p/2]

// ---- bf16 helpers ----
__device__ __forceinline__ uint32_t pack_bf16(__nv_bfloat16 a, __nv_bfloat16 b) {
    __nv_bfloat162 t; t.x = a; t.y = b;
    return *(uint32_t*)&t;
}
__device__ __forceinline__ uint2 split2(float x0, float x1) {
    __nv_bfloat16 h0 = __float2bfloat16_rn(x0);
    __nv_bfloat16 h1 = __float2bfloat16_rn(x1);
    float r0 = x0 - __bfloat162float(h0);
    float r1 = x1 - __bfloat162float(h1);
    uint2 o;
    o.x = pack_bf16(h0, h1);
    o.y = pack_bf16(__float2bfloat16_rn(r0), __float2bfloat16_rn(r1));
    return o;
}

#define MMA_BF16(d, a, b)                                                   \
  asm("mma.sync.aligned.m16n8k16.row.col.f32.bf16.bf16.f32 "                \
      "{%0,%1,%2,%3},{%4,%5,%6,%7},{%8,%9},{%0,%1,%2,%3};"                  \
      : "+f"(d[0]), "+f"(d[1]), "+f"(d[2]), "+f"(d[3])                      \
      : "r"(a[0]), "r"(a[1]), "r"(a[2]), "r"(a[3]), "r"(b[0]), "r"(b[1]))

__device__ __forceinline__ void cpa16(void* dst, const void* src) {
    uint32_t d = (uint32_t)__cvta_generic_to_shared(dst);
    asm volatile("cp.async.cg.shared.global [%0], [%1], 16;" :: "r"(d), "l"(src));
}
#define CP_COMMIT  asm volatile("cp.async.commit_group;")
#define CP_WAIT(n) asm volatile("cp.async.wait_group %0;" :: "n"(n))

#define SPAD 20   // uint2 row stride: 40 words = 8 mod 32 -> conflict-free

// ---- packed abs-dot: acc += |x1 + x2| * w  (per 32-bit half; no movs) ----
#define ABSDOT2(acc, x1, x2, w)                                             \
{                                                                           \
    ull t_;                                                                 \
    asm("add.rn.f32x2 %0, %1, %2;" : "=l"(t_) : "l"(x1), "l"(x2));          \
    t_ &= 0x7FFFFFFF7FFFFFFFULL;                                            \
    asm("fma.rn.f32x2 %0, %1, %2, %0;" : "+l"(acc) : "l"(t_), "l"(w));      \
}

#define UNPACK2(l, h, v) \
    asm("mov.b64 {%0, %1}, %2;" : "=f"(l), "=f"(h) : "l"(v))

// 16B-block permutation within a 64-float s1 row: blocks c=0..15,
// perm(c) = ((c&1)<<3) | (c>>1).  Readers: block tx <- c=2tx (p=8tx..8tx+3),
// block 8+tx <- c=2tx+1 (p=8tx+4..8tx+7). Conflict-free per 8-lane phase.
__device__ __forceinline__ int s1_pos(int p) {
    int c = p >> 2;
    int cp = ((c & 1) << 3) | (c >> 1);
    return cp * 4 + (p & 3);
}

// ---------------------------------------------------------------------------
// Kernel 0: presplit — 4 floats per thread.
// ---------------------------------------------------------------------------
__global__ __launch_bounds__(256)
void presplit_kernel(const float* __restrict__ enc, const float* __restrict__ dh,
                     const float* __restrict__ lo,  const float* __restrict__ We,
                     const float* __restrict__ Wt,  const float* __restrict__ Wl)
{
    const int z   = blockIdx.z;
    const int idx = blockIdx.x * 256 + threadIdx.x;
    if (z < 6) {
        const float* X; uint2* Y; int count4;
        switch (z) {
            case 0: X = enc; Y = g_encA; count4 = P_PIX  * E_DIM / 4; break;
            case 1: X = dh;  Y = g_dhA;  count4 = N_ROWS * E_DIM / 4; break;
            case 2: X = lo;  Y = g_loA;  count4 = N_ROWS * E_DIM / 4; break;
            case 3: X = We;  Y = g_WeP;  count4 = A_DIM  * E_DIM / 4; break;
            case 4: X = Wt;  Y = g_WtP;  count4 = A_DIM  * E_DIM / 4; break;
            default:X = Wl;  Y = g_WlP;  count4 = A_DIM  * E_DIM / 4; break;
        }
        if (idx < count4) {
            float4 v = *(const float4*)&X[4 * idx];
            uint2 u0 = split2(v.x, v.y);
            uint2 u1 = split2(v.z, v.w);
            uint4 pk; pk.x = u0.x; pk.y = u0.y; pk.z = u1.x; pk.w = u1.y;
            *(uint4*)&Y[2 * idx] = pk;
        }
    } else {
        if (idx < (P_PIX / 2) * (E_DIM / 2)) {
            int p2 = idx / (E_DIM / 2);
            int ec = (idx % (E_DIM / 2)) * 2;
            float2 r0 = *(const float2*)&enc[(2 * p2) * E_DIM + ec];
            float2 r1 = *(const float2*)&enc[(2 * p2 + 1) * E_DIM + ec];
            uint2 u0 = split2(r0.x, r1.x);
            uint2 u1 = split2(r0.y, r1.y);
            uint4 pk; pk.x = u0.x; pk.y = u0.y; pk.z = u1.x; pk.w = u1.y;
            *(uint4*)&g_encB[p2 * E_DIM + ec] = pk;
        }
    }
}

// ---------------------------------------------------------------------------
// Kernel 1: tc_attproj — C = A @ W^T + bias (M=1024, N=256, K=512), per z.
// CTA tile 64m x 32n, 128 threads, bf16 3-split mma, 3-stage cp.async pipe.
// ---------------------------------------------------------------------------
__global__ __launch_bounds__(128)
void tc_attproj(const float* __restrict__ be, const float* __restrict__ bt,
                const float* __restrict__ bl)
{
    __shared__ uint2 Apk[3][64][SPAD];
    __shared__ uint2 Bpk[3][32][SPAD];

    const int z = blockIdx.z;
    const uint2* Asrc = (z == 0) ? g_encA : (z == 1) ? g_dhA : g_loA;
    const uint2* Bsrc = (z == 0) ? g_WeP  : (z == 1) ? g_WtP : g_WlP;
    const float* bv   = (z == 0) ? be     : (z == 1) ? bt    : bl;
    float*       C    = (z == 0) ? g_att1 : (z == 1) ? g_att23 : g_att3;

    const int tid = threadIdx.x;
    const int m0  = blockIdx.y * 64;
    const int n0  = blockIdx.x * 32;

    const int lane = tid & 31, wid = tid >> 5;
    const int wm = (wid & 1) * 32;
    const int wn = (wid >> 1) * 16;
    const int g = lane >> 2, t = lane & 3;

    float acc[2][2][4] = {};

    const int KP_ROW = E_DIM / 2;

    #define STAGE_P(kt, b)                                                   \
    {                                                                        \
        int kpb = (kt) * 16;                                                 \
        _Pragma("unroll")                                                    \
        for (int j = 0; j < 4; j++) {                                        \
            int o = tid + 128 * j;                                           \
            int r = o >> 3, kpc = (o & 7) * 2;                               \
            cpa16(&Apk[b][r][kpc], Asrc + (m0 + r) * KP_ROW + kpb + kpc);    \
        }                                                                    \
        _Pragma("unroll")                                                    \
        for (int j = 0; j < 2; j++) {                                        \
            int o = tid + 128 * j;                                           \
            int r = o >> 3, kpc = (o & 7) * 2;                               \
            cpa16(&Bpk[b][r][kpc], Bsrc + (n0 + r) * KP_ROW + kpb + kpc);    \
        }                                                                    \
        CP_COMMIT;                                                           \
    }

    const int T = E_DIM / 32;              // 16 tiles
    STAGE_P(0, 0);
    STAGE_P(1, 1);
    for (int it = 0; it < T; it++) {
        const int b = it % 3;
        if (it + 1 < T) { CP_WAIT(1); } else { CP_WAIT(0); }
        __syncthreads();
        if (it + 2 < T) STAGE_P(it + 2, (it + 2) % 3);

        #pragma unroll
        for (int ks = 0; ks < 2; ks++) {
            const int kp0 = ks * 8;
            uint32_t Ah[2][4], Al[2][4];
            #pragma unroll
            for (int mf = 0; mf < 2; mf++) {
                int r = wm + mf * 16 + g;
                uint2 p00 = Apk[b][r][kp0 + t];
                uint2 p10 = Apk[b][r + 8][kp0 + t];
                uint2 p01 = Apk[b][r][kp0 + t + 4];
                uint2 p11 = Apk[b][r + 8][kp0 + t + 4];
                Ah[mf][0] = p00.x; Ah[mf][1] = p10.x; Ah[mf][2] = p01.x; Ah[mf][3] = p11.x;
                Al[mf][0] = p00.y; Al[mf][1] = p10.y; Al[mf][2] = p01.y; Al[mf][3] = p11.y;
            }
            uint32_t Bh[2][2], Bl[2][2];
            #pragma unroll
            for (int nf = 0; nf < 2; nf++) {
                int c = wn + nf * 8 + g;
                uint2 q0 = Bpk[b][c][kp0 + t];
                uint2 q1 = Bpk[b][c][kp0 + t + 4];
                Bh[nf][0] = q0.x; Bh[nf][1] = q1.x;
                Bl[nf][0] = q0.y; Bl[nf][1] = q1.y;
            }
            #pragma unroll
            for (int mf = 0; mf < 2; mf++)
                #pragma unroll
                for (int nf = 0; nf < 2; nf++) {
                    MMA_BF16(acc[mf][nf], Ah[mf], Bh[nf]);
                    MMA_BF16(acc[mf][nf], Ah[mf], Bl[nf]);
                    MMA_BF16(acc[mf][nf], Al[mf], Bh[nf]);
                }
        }
    }
    #undef STAGE_P

    #pragma unroll
    for (int mf = 0; mf < 2; mf++)
        #pragma unroll
        for (int nf = 0; nf < 2; nf++) {
            int r = m0 + wm + mf * 16 + g;
            int c = n0 + wn + nf * 8 + t * 2;
            float b0 = bv[c], b1 = bv[c + 1];
            *(float2*)&C[r * A_DIM + c] =
                make_float2(acc[mf][nf][0] + b0, acc[mf][nf][1] + b1);
            *(float2*)&C[(r + 8) * A_DIM + c] =
                make_float2(acc[mf][nf][2] + b0, acc[mf][nf][3] + b1);
        }
}

// ---------------------------------------------------------------------------
// Kernel 1b: c1_kernel — c1[p] = 0.5 * sum_a att1[p,a] * Wf[a]
// ---------------------------------------------------------------------------
__global__ __launch_bounds__(256)
void c1_kernel(const float* __restrict__ Wf)
{
    const int lane = threadIdx.x & 31;
    const int w    = threadIdx.x >> 5;
    const int p    = blockIdx.x * 8 + w;

    const float4* row = (const float4*)(g_att1 + p * A_DIM);
    const float4* wf  = (const float4*)Wf;

    float s = 0.0f;
    #pragma unroll
    for (int j = 0; j < 2; j++) {
        float4 a = row[lane + 32 * j];
        float4 b = wf [lane + 32 * j];
        s += a.x * b.x + a.y * b.y + a.z * b.z + a.w * b.w;
    }
    #pragma unroll
    for (int o = 16; o > 0; o >>= 1) s += __shfl_xor_sync(0xffffffffu, s, o);
    if (lane == 0) g_c1[p] = 0.5f * s;
}

// ---------------------------------------------------------------------------
// Kernel 2: att_main v8 — relu-decomposed, 8p x 4n microtile (2.25 B/elem).
//   g_att[n,p] = sum_a |att1[p,a] + s2[n,a]| * (Wf[a]/2)
// CTA tile 64p x 64n, 128 threads (tx=tid&7 -> 8p each, ty=tid>>3 -> 4n each).
// s1 rows use a 16B-block permutation so both x1 fragment loads are
// conflict-free; x2/w reads are per-phase broadcasts.
// ---------------------------------------------------------------------------
__global__ __launch_bounds__(128)
void att_main_v8(const float* __restrict__ Wf)
{
    __shared__ float s1  [32][68];    // [a][p-permuted], 64 used
    __shared__ float s23d[32][132];   // [a][2n] duplicated {v,v}, 128 used
    __shared__ float swd [2 * A_DIM]; // Wf/2 duplicated

    const int tid = threadIdx.x;
    const int tx  = tid & 7;          // p-group: 8 p each
    const int ty  = tid >> 3;         // n-group: 4 n each (0..15)
    const int p0  = blockIdx.x * 64;
    const int n0  = blockIdx.y * 64;

    #pragma unroll
    for (int i = tid; i < A_DIM; i += 128) {
        float w = Wf[i] * 0.5f;
        *(float2*)&swd[2 * i] = make_float2(w, w);
    }

    ull acc[4][4] = {};               // [n j][p-pair 0..3]

    for (int a0 = 0; a0 < A_DIM; a0 += 32) {
        __syncthreads();
        // s1: 32a x 64p = 2048 elems, 16 per thread (coalesced along a)
        #pragma unroll
        for (int i = 0; i < 16; i++) {
            int e = tid + 128 * i;
            int a = e & 31, r = e >> 5;          // r = p-idx 0..63
            s1[a][s1_pos(r)] = g_att1[(p0 + r) * A_DIM + a0 + a];
        }
        // s23d: 32a x 64n, 16 per thread, duplicated
        #pragma unroll
        for (int i = 0; i < 16; i++) {
            int e = tid + 128 * i;
            int a = e & 31, r = e >> 5;          // r = n-idx 0..63
            float v = g_att23[(n0 + r) * A_DIM + a0 + a]
                    + g_att3 [(n0 + r) * A_DIM + a0 + a];
            *(float2*)&s23d[a][2 * r] = make_float2(v, v);
        }
        __syncthreads();

        #pragma unroll 4
        for (int a = 0; a < 32; a++) {
            ulonglong2 x1a = *(const ulonglong2*)&s1[a][4 * tx];        // p 8tx..8tx+3
            ulonglong2 x1b = *(const ulonglong2*)&s1[a][32 + 4 * tx];   // p 8tx+4..8tx+7
            ulonglong2 x2a = *(const ulonglong2*)&s23d[a][8 * ty];      // n 4ty, 4ty+1
            ulonglong2 x2b = *(const ulonglong2*)&s23d[a][8 * ty + 4];  // n 4ty+2, 4ty+3
            ull w = *(const ull*)&swd[2 * (a0 + a)];
            ABSDOT2(acc[0][0], x1a.x, x2a.x, w); ABSDOT2(acc[0][1], x1a.y, x2a.x, w);
            ABSDOT2(acc[0][2], x1b.x, x2a.x, w); ABSDOT2(acc[0][3], x1b.y, x2a.x, w);
            ABSDOT2(acc[1][0], x1a.x, x2a.y, w); ABSDOT2(acc[1][1], x1a.y, x2a.y, w);
            ABSDOT2(acc[1][2], x1b.x, x2a.y, w); ABSDOT2(acc[1][3], x1b.y, x2a.y, w);
            ABSDOT2(acc[2][0], x1a.x, x2b.x, w); ABSDOT2(acc[2][1], x1a.y, x2b.x, w);
            ABSDOT2(acc[2][2], x1b.x, x2b.x, w); ABSDOT2(acc[2][3], x1b.y, x2b.x, w);
            ABSDOT2(acc[3][0], x1a.x, x2b.y, w); ABSDOT2(acc[3][1], x1a.y, x2b.y, w);
            ABSDOT2(acc[3][2], x1b.x, x2b.y, w); ABSDOT2(acc[3][3], x1b.y, x2b.y, w);
        }
    }

    #pragma unroll
    for (int j = 0; j < 4; j++) {
        int n = n0 + ty * 4 + j;
        float l0, h0, l1, h1, l2, h2, l3, h3;
        UNPACK2(l0, h0, acc[j][0]);
        UNPACK2(l1, h1, acc[j][1]);
        UNPACK2(l2, h2, acc[j][2]);
        UNPACK2(l3, h3, acc[j][3]);
        *(float4*)&g_att[n * P_PIX + p0 + 8 * tx]     = make_float4(l0, h0, l1, h1);
        *(float4*)&g_att[n * P_PIX + p0 + 8 * tx + 4] = make_float4(l2, h2, l3, h3);
    }
}

// ---------------------------------------------------------------------------
// Kernel 3: softmax v4 — adds c1[p]; 1 warp/row, grid 256 x 128.
// ---------------------------------------------------------------------------
__global__ __launch_bounds__(128)
void softmax_v4(float* __restrict__ alpha)
{
    const int tid  = threadIdx.x;
    const int lane = tid & 31;
    const int w    = tid >> 5;
    const int n    = blockIdx.x * 4 + w;

    const float4* row  = (const float4*)(g_att + n * P_PIX);
    const float4* c1r  = (const float4*)g_c1;

    float4 v[8];
    #pragma unroll
    for (int j = 0; j < 8; j++) {
        float4 x = row[lane + 32 * j];
        float4 c = c1r[lane + 32 * j];
        v[j] = make_float4(x.x + c.x, x.y + c.y, x.z + c.z, x.w + c.w);
    }

    float m = -1e30f;
    #pragma unroll
    for (int j = 0; j < 8; j++)
        m = fmaxf(m, fmaxf(fmaxf(v[j].x, v[j].y), fmaxf(v[j].z, v[j].w)));
    #pragma unroll
    for (int o = 16; o > 0; o >>= 1) m = fmaxf(m, __shfl_xor_sync(0xffffffffu, m, o));

    float s = 0.0f;
    #pragma unroll
    for (int j = 0; j < 8; j++) {
        v[j].x = __expf(v[j].x - m); s += v[j].x;
        v[j].y = __expf(v[j].y - m); s += v[j].y;
        v[j].z = __expf(v[j].z - m); s += v[j].z;
        v[j].w = __expf(v[j].w - m); s += v[j].w;
    }
    #pragma unroll
    for (int o = 16; o > 0; o >>= 1) s += __shfl_xor_sync(0xffffffffu, s, o);
    const float inv = 1.0f / s;

    float4* arow = (float4*)(alpha + n * P_PIX);
    uint4*  prow = (uint4*)(g_alphaP + n * (P_PIX / 2));
    #pragma unroll
    for (int j = 0; j < 8; j++) {
        float a0 = v[j].x * inv, a1 = v[j].y * inv;
        float a2 = v[j].z * inv, a3 = v[j].w * inv;
        arow[lane + 32 * j] = make_float4(a0, a1, a2, a3);
        uint2 u0 = split2(a0, a1);
        uint2 u1 = split2(a2, a3);
        uint4 pk; pk.x = u0.x; pk.y = u0.y; pk.z = u1.x; pk.w = u1.y;
        prow[lane + 32 * j] = pk;
    }
}

// ---------------------------------------------------------------------------
// Kernel 4: tc_gemm_ab — awe = alpha @ enc  (M=1024, N=512, K=1024)
// CTA tile 64m x 32n, 128 threads, bf16 3-split, 3-stage cp.async pipe.
// ---------------------------------------------------------------------------
__global__ __launch_bounds__(128)
void tc_gemm_ab(float* __restrict__ C)
{
    __shared__ uint2 Apk[3][64][SPAD];
    __shared__ uint2 Bpk[3][16][36];

    const int tid = threadIdx.x;
    const int m0  = blockIdx.y * 64;
    const int n0  = blockIdx.x * 32;

    const int lane = tid & 31, wid = tid >> 5;
    const int wm = (wid & 1) * 32;
    const int wn = (wid >> 1) * 16;
    const int g = lane >> 2, t = lane & 3;

    float acc[2][2][4] = {};

    #define STAGE_G(kt, b)                                                    \
    {                                                                         \
        int kpb = (kt) * 16;                                                  \
        _Pragma("unroll")                                                     \
        for (int j = 0; j < 4; j++) {                                         \
            int o = tid + 128 * j;                                            \
            int r = o >> 3, kpc = (o & 7) * 2;                                \
            cpa16(&Apk[b][r][kpc],                                            \
                  g_alphaP + (m0 + r) * (P_PIX / 2) + kpb + kpc);             \
        }                                                                     \
        _Pragma("unroll")                                                     \
        for (int j = 0; j < 2; j++) {                                         \
            int o = tid + 128 * j;                                            \
            int kp = o >> 4, nc = (o & 15) * 2;                               \
            cpa16(&Bpk[b][kp][nc], g_encB + (kpb + kp) * E_DIM + n0 + nc);    \
        }                                                                     \
        CP_COMMIT;                                                            \
    }

    const int T = P_PIX / 32;              // 32 tiles
    STAGE_G(0, 0);
    STAGE_G(1, 1);
    for (int it = 0; it < T; it++) {
        const int b = it % 3;
        if (it + 1 < T) { CP_WAIT(1); } else { CP_WAIT(0); }
        __syncthreads();
        if (it + 2 < T) STAGE_G(it + 2, (it + 2) % 3);

        #pragma unroll
        for (int ks = 0; ks < 2; ks++) {
            const int kp0 = ks * 8;
            uint32_t Ah[2][4], Al[2][4];
            #pragma unroll
            for (int mf = 0; mf < 2; mf++) {
                int r = wm + mf * 16 + g;
                uint2 p00 = Apk[b][r][kp0 + t];
                uint2 p10 = Apk[b][r + 8][kp0 + t];
                uint2 p01 = Apk[b][r][kp0 + t + 4];
                uint2 p11 = Apk[b][r + 8][kp0 + t + 4];
                Ah[mf][0] = p00.x; Ah[mf][1] = p10.x; Ah[mf][2] = p01.x; Ah[mf][3] = p11.x;
                Al[mf][0] = p00.y; Al[mf][1] = p10.y; Al[mf][2] = p01.y; Al[mf][3] = p11.y;
            }
            uint32_t Bh[2][2], Bl[2][2];
            #pragma unroll
            for (int nf = 0; nf < 2; nf++) {
                int c = wn + nf * 8 + g;
                uint2 q0 = Bpk[b][kp0 + t][c];
                uint2 q1 = Bpk[b][kp0 + t + 4][c];
                Bh[nf][0] = q0.x; Bh[nf][1] = q1.x;
                Bl[nf][0] = q0.y; Bl[nf][1] = q1.y;
            }
            #pragma unroll
            for (int mf = 0; mf < 2; mf++)
                #pragma unroll
                for (int nf = 0; nf < 2; nf++) {
                    MMA_BF16(acc[mf][nf], Ah[mf], Bh[nf]);
                    MMA_BF16(acc[mf][nf], Ah[mf], Bl[nf]);
                    MMA_BF16(acc[mf][nf], Al[mf], Bh[nf]);
                }
        }
    }
    #undef STAGE_G

    #pragma unroll
    for (int mf = 0; mf < 2; mf++)
        #pragma unroll
        for (int nf = 0; nf < 2; nf++) {
            int r = m0 + wm + mf * 16 + g;
            int c = n0 + wn + nf * 8 + t * 2;
            *(float2*)&C[r * E_DIM + c] =
                make_float2(acc[mf][nf][0], acc[mf][nf][1]);
            *(float2*)&C[(r + 8) * E_DIM + c] =
                make_float2(acc[mf][nf][2], acc[mf][nf][3]);
        }
}

// ---------------------------------------------------------------------------
// Launch
// ---------------------------------------------------------------------------
extern "C" void kernel_launch(void* const* d_in, const int* in_sizes, int n_in,
                              void* d_out, int out_size)
{
    (void)in_sizes; (void)n_in; (void)out_size;
    const float* enc = (const float*)d_in[0];
    const float* dh  = (const float*)d_in[1];
    const float* lo  = (const float*)d_in[2];
    const float* We  = (const float*)d_in[3];
    const float* be  = (const float*)d_in[4];
    const float* Wt  = (const float*)d_in[5];
    const float* bt  = (const float*)d_in[6];
    const float* Wl  = (const float*)d_in[7];
    const float* bl  = (const float*)d_in[8];
    const float* Wf  = (const float*)d_in[9];
    // d_in[10] = bf: uniform shift, cancels in softmax.

    float* awe   = (float*)d_out;
    float* alpha = (float*)d_out + N_ROWS * E_DIM;

    dim3 g0(512, 1, 7);
    presplit_kernel<<<g0, 256>>>(enc, dh, lo, We, Wt, Wl);

    dim3 g1(A_DIM / 32, 1024 / 64, 3);
    tc_attproj<<<g1, 128>>>(be, bt, bl);

    c1_kernel<<<P_PIX / 8, 256>>>(Wf);

    dim3 g2(P_PIX / 64, N_ROWS / 64);
    att_main_v8<<<g2, 128>>>(Wf);

    softmax_v4<<<N_ROWS / 4, 128>>>(alpha);

    dim3 g4(E_DIM / 32, N_ROWS / 64);
    tc_gemm_ab<<<g4, 128>>>(awe);
}

// round 17
// speedup vs baseline: 1.1030x; 1.1030x over previous
#include <cuda_runtime.h>
#include <cuda_bf16.h>
#include <stdint.h>

typedef unsigned long long ull;

#define N_ROWS 1024   // N
#define P_PIX  1024   // P
#define E_DIM  512    // ENC / TAG / LANG
#define A_DIM  256    // ATT

// fp32 scratch
__device__ float g_att1 [P_PIX * A_DIM];    // (P, A)  enc@We^T + be
__device__ float g_att23[N_ROWS * A_DIM];   // (N, A)  dh@Wt^T + bt
__device__ float g_att3 [N_ROWS * A_DIM];   // (N, A)  lo@Wl^T + bl
__device__ float g_attP0[N_ROWS * P_PIX];   // partial |x|*w/2, a in [0,128)
__device__ float g_attP1[N_ROWS * P_PIX];   // partial |x|*w/2, a in [128,256)
__device__ float g_c1   [P_PIX];            // c1[p] = 0.5*sum_a att1[p,a]*Wf[a]

// pre-split packed scratch: uint2 = {bf16x2 hi (k even,k odd), bf16x2 lo}
__device__ uint2 g_encA [P_PIX  * E_DIM / 2];   // [p][e/2]
__device__ uint2 g_dhA  [N_ROWS * E_DIM / 2];   // [n][e/2]
__device__ uint2 g_loA  [N_ROWS * E_DIM / 2];   // [n][e/2]
__device__ uint2 g_WeP  [A_DIM  * E_DIM / 2];   // [a][e/2]
__device__ uint2 g_WtP  [A_DIM  * E_DIM / 2];
__device__ uint2 g_WlP  [A_DIM  * E_DIM / 2];
__device__ uint2 g_encB [(P_PIX / 2) * E_DIM];  // [p/2][e]
__device__ uint2 g_alphaP[N_ROWS * P_PIX / 2];  // [n][p/2]

// ---- bf16 helpers ----
__device__ __forceinline__ uint32_t pack_bf16(__nv_bfloat16 a, __nv_bfloat16 b) {
    __nv_bfloat162 t; t.x = a; t.y = b;
    return *(uint32_t*)&t;
}
__device__ __forceinline__ uint2 split2(float x0, float x1) {
    __nv_bfloat16 h0 = __float2bfloat16_rn(x0);
    __nv_bfloat16 h1 = __float2bfloat16_rn(x1);
    float r0 = x0 - __bfloat162float(h0);
    float r1 = x1 - __bfloat162float(h1);
    uint2 o;
    o.x = pack_bf16(h0, h1);
    o.y = pack_bf16(__float2bfloat16_rn(r0), __float2bfloat16_rn(r1));
    return o;
}

#define MMA_BF16(d, a, b)                                                   \
  asm("mma.sync.aligned.m16n8k16.row.col.f32.bf16.bf16.f32 "                \
      "{%0,%1,%2,%3},{%4,%5,%6,%7},{%8,%9},{%0,%1,%2,%3};"                  \
      : "+f"(d[0]), "+f"(d[1]), "+f"(d[2]), "+f"(d[3])                      \
      : "r"(a[0]), "r"(a[1]), "r"(a[2]), "r"(a[3]), "r"(b[0]), "r"(b[1]))

__device__ __forceinline__ void cpa16(void* dst, const void* src) {
    uint32_t d = (uint32_t)__cvta_generic_to_shared(dst);
    asm volatile("cp.async.cg.shared.global [%0], [%1], 16;" :: "r"(d), "l"(src));
}
#define CP_COMMIT  asm volatile("cp.async.commit_group;")
#define CP_WAIT(n) asm volatile("cp.async.wait_group %0;" :: "n"(n))

#define SPAD 20   // uint2 row stride: 40 words = 8 mod 32 -> conflict-free

// ---- packed abs-dot: acc += |x1 + x2| * w  (per 32-bit half; no movs) ----
#define ABSDOT2(acc, x1, x2, w)                                             \
{                                                                           \
    ull t_;                                                                 \
    asm("add.rn.f32x2 %0, %1, %2;" : "=l"(t_) : "l"(x1), "l"(x2));          \
    t_ &= 0x7FFFFFFF7FFFFFFFULL;                                            \
    asm("fma.rn.f32x2 %0, %1, %2, %0;" : "+l"(acc) : "l"(t_), "l"(w));      \
}

#define UNPACK2(l, h, v) \
    asm("mov.b64 {%0, %1}, %2;" : "=f"(l), "=f"(h) : "l"(v))

// ---------------------------------------------------------------------------
// Kernel 0: presplit — 4 floats per thread.
// ---------------------------------------------------------------------------
__global__ __launch_bounds__(256)
void presplit_kernel(const float* __restrict__ enc, const float* __restrict__ dh,
                     const float* __restrict__ lo,  const float* __restrict__ We,
                     const float* __restrict__ Wt,  const float* __restrict__ Wl)
{
    const int z   = blockIdx.z;
    const int idx = blockIdx.x * 256 + threadIdx.x;
    if (z < 6) {
        const float* X; uint2* Y; int count4;
        switch (z) {
            case 0: X = enc; Y = g_encA; count4 = P_PIX  * E_DIM / 4; break;
            case 1: X = dh;  Y = g_dhA;  count4 = N_ROWS * E_DIM / 4; break;
            case 2: X = lo;  Y = g_loA;  count4 = N_ROWS * E_DIM / 4; break;
            case 3: X = We;  Y = g_WeP;  count4 = A_DIM  * E_DIM / 4; break;
            case 4: X = Wt;  Y = g_WtP;  count4 = A_DIM  * E_DIM / 4; break;
            default:X = Wl;  Y = g_WlP;  count4 = A_DIM  * E_DIM / 4; break;
        }
        if (idx < count4) {
            float4 v = *(const float4*)&X[4 * idx];
            uint2 u0 = split2(v.x, v.y);
            uint2 u1 = split2(v.z, v.w);
            uint4 pk; pk.x = u0.x; pk.y = u0.y; pk.z = u1.x; pk.w = u1.y;
            *(uint4*)&Y[2 * idx] = pk;
        }
    } else {
        if (idx < (P_PIX / 2) * (E_DIM / 2)) {
            int p2 = idx / (E_DIM / 2);
            int ec = (idx % (E_DIM / 2)) * 2;
            float2 r0 = *(const float2*)&enc[(2 * p2) * E_DIM + ec];
            float2 r1 = *(const float2*)&enc[(2 * p2 + 1) * E_DIM + ec];
            uint2 u0 = split2(r0.x, r1.x);
            uint2 u1 = split2(r0.y, r1.y);
            uint4 pk; pk.x = u0.x; pk.y = u0.y; pk.z = u1.x; pk.w = u1.y;
            *(uint4*)&g_encB[p2 * E_DIM + ec] = pk;
        }
    }
}

// ---------------------------------------------------------------------------
// Kernel 1: tc_attproj — C = A @ W^T + bias (M=1024, N=256, K=512), per z.
// CTA tile 64m x 32n, 128 threads, bf16 3-split mma, 3-stage cp.async pipe.
// ---------------------------------------------------------------------------
__global__ __launch_bounds__(128)
void tc_attproj(const float* __restrict__ be, const float* __restrict__ bt,
                const float* __restrict__ bl)
{
    __shared__ uint2 Apk[3][64][SPAD];
    __shared__ uint2 Bpk[3][32][SPAD];

    const int z = blockIdx.z;
    const uint2* Asrc = (z == 0) ? g_encA : (z == 1) ? g_dhA : g_loA;
    const uint2* Bsrc = (z == 0) ? g_WeP  : (z == 1) ? g_WtP : g_WlP;
    const float* bv   = (z == 0) ? be     : (z == 1) ? bt    : bl;
    float*       C    = (z == 0) ? g_att1 : (z == 1) ? g_att23 : g_att3;

    const int tid = threadIdx.x;
    const int m0  = blockIdx.y * 64;
    const int n0  = blockIdx.x * 32;

    const int lane = tid & 31, wid = tid >> 5;
    const int wm = (wid & 1) * 32;
    const int wn = (wid >> 1) * 16;
    const int g = lane >> 2, t = lane & 3;

    float acc[2][2][4] = {};

    const int KP_ROW = E_DIM / 2;

    #define STAGE_P(kt, b)                                                   \
    {                                                                        \
        int kpb = (kt) * 16;                                                 \
        _Pragma("unroll")                                                    \
        for (int j = 0; j < 4; j++) {                                        \
            int o = tid + 128 * j;                                           \
            int r = o >> 3, kpc = (o & 7) * 2;                               \
            cpa16(&Apk[b][r][kpc], Asrc + (m0 + r) * KP_ROW + kpb + kpc);    \
        }                                                                    \
        _Pragma("unroll")                                                    \
        for (int j = 0; j < 2; j++) {                                        \
            int o = tid + 128 * j;                                           \
            int r = o >> 3, kpc = (o & 7) * 2;                               \
            cpa16(&Bpk[b][r][kpc], Bsrc + (n0 + r) * KP_ROW + kpb + kpc);    \
        }                                                                    \
        CP_COMMIT;                                                           \
    }

    const int T = E_DIM / 32;              // 16 tiles
    STAGE_P(0, 0);
    STAGE_P(1, 1);
    for (int it = 0; it < T; it++) {
        const int b = it % 3;
        if (it + 1 < T) { CP_WAIT(1); } else { CP_WAIT(0); }
        __syncthreads();
        if (it + 2 < T) STAGE_P(it + 2, (it + 2) % 3);

        #pragma unroll
        for (int ks = 0; ks < 2; ks++) {
            const int kp0 = ks * 8;
            uint32_t Ah[2][4], Al[2][4];
            #pragma unroll
            for (int mf = 0; mf < 2; mf++) {
                int r = wm + mf * 16 + g;
                uint2 p00 = Apk[b][r][kp0 + t];
                uint2 p10 = Apk[b][r + 8][kp0 + t];
                uint2 p01 = Apk[b][r][kp0 + t + 4];
                uint2 p11 = Apk[b][r + 8][kp0 + t + 4];
                Ah[mf][0] = p00.x; Ah[mf][1] = p10.x; Ah[mf][2] = p01.x; Ah[mf][3] = p11.x;
                Al[mf][0] = p00.y; Al[mf][1] = p10.y; Al[mf][2] = p01.y; Al[mf][3] = p11.y;
            }
            uint32_t Bh[2][2], Bl[2][2];
            #pragma unroll
            for (int nf = 0; nf < 2; nf++) {
                int c = wn + nf * 8 + g;
                uint2 q0 = Bpk[b][c][kp0 + t];
                uint2 q1 = Bpk[b][c][kp0 + t + 4];
                Bh[nf][0] = q0.x; Bh[nf][1] = q1.x;
                Bl[nf][0] = q0.y; Bl[nf][1] = q1.y;
            }
            #pragma unroll
            for (int mf = 0; mf < 2; mf++)
                #pragma unroll
                for (int nf = 0; nf < 2; nf++) {
                    MMA_BF16(acc[mf][nf], Ah[mf], Bh[nf]);
                    MMA_BF16(acc[mf][nf], Ah[mf], Bl[nf]);
                    MMA_BF16(acc[mf][nf], Al[mf], Bh[nf]);
                }
        }
    }
    #undef STAGE_P

    #pragma unroll
    for (int mf = 0; mf < 2; mf++)
        #pragma unroll
        for (int nf = 0; nf < 2; nf++) {
            int r = m0 + wm + mf * 16 + g;
            int c = n0 + wn + nf * 8 + t * 2;
            float b0 = bv[c], b1 = bv[c + 1];
            *(float2*)&C[r * A_DIM + c] =
                make_float2(acc[mf][nf][0] + b0, acc[mf][nf][1] + b1);
            *(float2*)&C[(r + 8) * A_DIM + c] =
                make_float2(acc[mf][nf][2] + b0, acc[mf][nf][3] + b1);
        }
}

// ---------------------------------------------------------------------------
// Kernel 1b: c1_kernel — c1[p] = 0.5 * sum_a att1[p,a] * Wf[a]
// ---------------------------------------------------------------------------
__global__ __launch_bounds__(256)
void c1_kernel(const float* __restrict__ Wf)
{
    const int lane = threadIdx.x & 31;
    const int w    = threadIdx.x >> 5;
    const int p    = blockIdx.x * 8 + w;

    const float4* row = (const float4*)(g_att1 + p * A_DIM);
    const float4* wf  = (const float4*)Wf;

    float s = 0.0f;
    #pragma unroll
    for (int j = 0; j < 2; j++) {
        float4 a = row[lane + 32 * j];
        float4 b = wf [lane + 32 * j];
        s += a.x * b.x + a.y * b.y + a.z * b.z + a.w * b.w;
    }
    #pragma unroll
    for (int o = 16; o > 0; o >>= 1) s += __shfl_xor_sync(0xffffffffu, s, o);
    if (lane == 0) g_c1[p] = 0.5f * s;
}

// ---------------------------------------------------------------------------
// Kernel 2: att_main v9 — relu-decomposed, split-A (z halves of a-range).
//   g_attP{z}[n,p] = sum_{a in half z} |att1[p,a] + s2[n,a]| * (Wf[a]/2)
// 64p x 64n tile, 256 threads, 4x4 microtile (v6 shape). Grid (16,16,2).
// ---------------------------------------------------------------------------
__global__ __launch_bounds__(256)
void att_main_v9(const float* __restrict__ Wf)
{
    __shared__ float s1  [32][68];    // [a][p]
    __shared__ float s23d[32][132];   // [a][2n] duplicated {v,v}
    __shared__ float swd [2 * 128];   // Wf/2 duplicated, this half only

    const int tid = threadIdx.x;
    const int tx  = tid & 15;         // p-group (4 p = 2 pairs)
    const int ty  = tid >> 4;         // n-group (4 n)
    const int p0  = blockIdx.x * 64;
    const int n0  = blockIdx.y * 64;
    const int ab0 = blockIdx.z * 128; // a-range base (half)
    float* out    = blockIdx.z ? g_attP1 : g_attP0;

    if (tid < 128) {
        float w = Wf[ab0 + tid] * 0.5f;
        *(float2*)&swd[2 * tid] = make_float2(w, w);
    }

    ull acc[4][2] = {};               // [n j][p-pair]

    for (int ac = 0; ac < 128; ac += 32) {
        const int a0 = ab0 + ac;
        __syncthreads();
        #pragma unroll
        for (int i = 0; i < 8; i++) {
            int e = tid + 256 * i;
            int a = e & 31, r = e >> 5;     // a 0..31, r 0..63
            s1[a][r] = g_att1[(p0 + r) * A_DIM + a0 + a];
            float v  = g_att23[(n0 + r) * A_DIM + a0 + a]
                     + g_att3 [(n0 + r) * A_DIM + a0 + a];
            *(float2*)&s23d[a][2 * r] = make_float2(v, v);
        }
        __syncthreads();

        #pragma unroll 4
        for (int a = 0; a < 32; a++) {
            ulonglong2 x1  = *(const ulonglong2*)&s1  [a][tx * 4];
            ulonglong2 x2a = *(const ulonglong2*)&s23d[a][ty * 8];
            ulonglong2 x2b = *(const ulonglong2*)&s23d[a][ty * 8 + 4];
            ull w = *(const ull*)&swd[2 * (ac + a)];
            ABSDOT2(acc[0][0], x1.x, x2a.x, w); ABSDOT2(acc[0][1], x1.y, x2a.x, w);
            ABSDOT2(acc[1][0], x1.x, x2a.y, w); ABSDOT2(acc[1][1], x1.y, x2a.y, w);
            ABSDOT2(acc[2][0], x1.x, x2b.x, w); ABSDOT2(acc[2][1], x1.y, x2b.x, w);
            ABSDOT2(acc[3][0], x1.x, x2b.y, w); ABSDOT2(acc[3][1], x1.y, x2b.y, w);
        }
    }

    #pragma unroll
    for (int j = 0; j < 4; j++) {
        float l0, h0, l1, h1;
        UNPACK2(l0, h0, acc[j][0]);
        UNPACK2(l1, h1, acc[j][1]);
        *(float4*)&out[(n0 + ty * 4 + j) * P_PIX + p0 + tx * 4] =
            make_float4(l0, h0, l1, h1);
    }
}

// ---------------------------------------------------------------------------
// Kernel 3: softmax v5 — scores = P0 + P1 + c1; 1 warp/row, grid 256 x 128.
// ---------------------------------------------------------------------------
__global__ __launch_bounds__(128)
void softmax_v5(float* __restrict__ alpha)
{
    const int tid  = threadIdx.x;
    const int lane = tid & 31;
    const int w    = tid >> 5;
    const int n    = blockIdx.x * 4 + w;

    const float4* r0 = (const float4*)(g_attP0 + n * P_PIX);
    const float4* r1 = (const float4*)(g_attP1 + n * P_PIX);
    const float4* c1r = (const float4*)g_c1;

    float4 v[8];
    #pragma unroll
    for (int j = 0; j < 8; j++) {
        float4 a = r0[lane + 32 * j];
        float4 b = r1[lane + 32 * j];
        float4 c = c1r[lane + 32 * j];
        v[j] = make_float4(a.x + b.x + c.x, a.y + b.y + c.y,
                           a.z + b.z + c.z, a.w + b.w + c.w);
    }

    float m = -1e30f;
    #pragma unroll
    for (int j = 0; j < 8; j++)
        m = fmaxf(m, fmaxf(fmaxf(v[j].x, v[j].y), fmaxf(v[j].z, v[j].w)));
    #pragma unroll
    for (int o = 16; o > 0; o >>= 1) m = fmaxf(m, __shfl_xor_sync(0xffffffffu, m, o));

    float s = 0.0f;
    #pragma unroll
    for (int j = 0; j < 8; j++) {
        v[j].x = __expf(v[j].x - m); s += v[j].x;
        v[j].y = __expf(v[j].y - m); s += v[j].y;
        v[j].z = __expf(v[j].z - m); s += v[j].z;
        v[j].w = __expf(v[j].w - m); s += v[j].w;
    }
    #pragma unroll
    for (int o = 16; o > 0; o >>= 1) s += __shfl_xor_sync(0xffffffffu, s, o);
    const float inv = 1.0f / s;

    float4* arow = (float4*)(alpha + n * P_PIX);
    uint4*  prow = (uint4*)(g_alphaP + n * (P_PIX / 2));
    #pragma unroll
    for (int j = 0; j < 8; j++) {
        float a0 = v[j].x * inv, a1 = v[j].y * inv;
        float a2 = v[j].z * inv, a3 = v[j].w * inv;
        arow[lane + 32 * j] = make_float4(a0, a1, a2, a3);
        uint2 u0 = split2(a0, a1);
        uint2 u1 = split2(a2, a3);
        uint4 pk; pk.x = u0.x; pk.y = u0.y; pk.z = u1.x; pk.w = u1.y;
        prow[lane + 32 * j] = pk;
    }
}

// ---------------------------------------------------------------------------
// Kernel 4: tc_gemm_ab — awe = alpha @ enc  (M=1024, N=512, K=1024)
// CTA tile 64m x 32n, 128 threads, bf16 3-split, 3-stage cp.async pipe.
// ---------------------------------------------------------------------------
__global__ __launch_bounds__(128)
void tc_gemm_ab(float* __restrict__ C)
{
    __shared__ uint2 Apk[3][64][SPAD];
    __shared__ uint2 Bpk[3][16][36];

    const int tid = threadIdx.x;
    const int m0  = blockIdx.y * 64;
    const int n0  = blockIdx.x * 32;

    const int lane = tid & 31, wid = tid >> 5;
    const int wm = (wid & 1) * 32;
    const int wn = (wid >> 1) * 16;
    const int g = lane >> 2, t = lane & 3;

    float acc[2][2][4] = {};

    #define STAGE_G(kt, b)                                                    \
    {                                                                         \
        int kpb = (kt) * 16;                                                  \
        _Pragma("unroll")                                                     \
        for (int j = 0; j < 4; j++) {                                         \
            int o = tid + 128 * j;                                            \
            int r = o >> 3, kpc = (o & 7) * 2;                                \
            cpa16(&Apk[b][r][kpc],                                            \
                  g_alphaP + (m0 + r) * (P_PIX / 2) + kpb + kpc);             \
        }                                                                     \
        _Pragma("unroll")                                                     \
        for (int j = 0; j < 2; j++) {                                         \
            int o = tid + 128 * j;                                            \
            int kp = o >> 4, nc = (o & 15) * 2;                               \
            cpa16(&Bpk[b][kp][nc], g_encB + (kpb + kp) * E_DIM + n0 + nc);    \
        }                                                                     \
        CP_COMMIT;                                                            \
    }

    const int T = P_PIX / 32;              // 32 tiles
    STAGE_G(0, 0);
    STAGE_G(1, 1);
    for (int it = 0; it < T; it++) {
        const int b = it % 3;
        if (it + 1 < T) { CP_WAIT(1); } else { CP_WAIT(0); }
        __syncthreads();
        if (it + 2 < T) STAGE_G(it + 2, (it + 2) % 3);

        #pragma unroll
        for (int ks = 0; ks < 2; ks++) {
            const int kp0 = ks * 8;
            uint32_t Ah[2][4], Al[2][4];
            #pragma unroll
            for (int mf = 0; mf < 2; mf++) {
                int r = wm + mf * 16 + g;
                uint2 p00 = Apk[b][r][kp0 + t];
                uint2 p10 = Apk[b][r + 8][kp0 + t];
                uint2 p01 = Apk[b][r][kp0 + t + 4];
                uint2 p11 = Apk[b][r + 8][kp0 + t + 4];
                Ah[mf][0] = p00.x; Ah[mf][1] = p10.x; Ah[mf][2] = p01.x; Ah[mf][3] = p11.x;
                Al[mf][0] = p00.y; Al[mf][1] = p10.y; Al[mf][2] = p01.y; Al[mf][3] = p11.y;
            }
            uint32_t Bh[2][2], Bl[2][2];
            #pragma unroll
            for (int nf = 0; nf < 2; nf++) {
                int c = wn + nf * 8 + g;
                uint2 q0 = Bpk[b][kp0 + t][c];
                uint2 q1 = Bpk[b][kp0 + t + 4][c];
                Bh[nf][0] = q0.x; Bh[nf][1] = q1.x;
                Bl[nf][0] = q0.y; Bl[nf][1] = q1.y;
            }
            #pragma unroll
            for (int mf = 0; mf < 2; mf++)
                #pragma unroll
                for (int nf = 0; nf < 2; nf++) {
                    MMA_BF16(acc[mf][nf], Ah[mf], Bh[nf]);
                    MMA_BF16(acc[mf][nf], Ah[mf], Bl[nf]);
                    MMA_BF16(acc[mf][nf], Al[mf], Bh[nf]);
                }
        }
    }
    #undef STAGE_G

    #pragma unroll
    for (int mf = 0; mf < 2; mf++)
        #pragma unroll
        for (int nf = 0; nf < 2; nf++) {
            int r = m0 + wm + mf * 16 + g;
            int c = n0 + wn + nf * 8 + t * 2;
            *(float2*)&C[r * E_DIM + c] =
                make_float2(acc[mf][nf][0], acc[mf][nf][1]);
            *(float2*)&C[(r + 8) * E_DIM + c] =
                make_float2(acc[mf][nf][2], acc[mf][nf][3]);
        }
}

// ---------------------------------------------------------------------------
// Launch
// ---------------------------------------------------------------------------
extern "C" void kernel_launch(void* const* d_in, const int* in_sizes, int n_in,
                              void* d_out, int out_size)
{
    (void)in_sizes; (void)n_in; (void)out_size;
    const float* enc = (const float*)d_in[0];
    const float* dh  = (const float*)d_in[1];
    const float* lo  = (const float*)d_in[2];
    const float* We  = (const float*)d_in[3];
    const float* be  = (const float*)d_in[4];
    const float* Wt  = (const float*)d_in[5];
    const float* bt  = (const float*)d_in[6];
    const float* Wl  = (const float*)d_in[7];
    const float* bl  = (const float*)d_in[8];
    const float* Wf  = (const float*)d_in[9];
    // d_in[10] = bf: uniform shift, cancels in softmax.

    float* awe   = (float*)d_out;
    float* alpha = (float*)d_out + N_ROWS * E_DIM;

    dim3 g0(512, 1, 7);
    presplit_kernel<<<g0, 256>>>(enc, dh, lo, We, Wt, Wl);

    dim3 g1(A_DIM / 32, 1024 / 64, 3);
    tc_attproj<<<g1, 128>>>(be, bt, bl);

    c1_kernel<<<P_PIX / 8, 256>>>(Wf);

    dim3 g2(P_PIX / 64, N_ROWS / 64, 2);
    att_main_v9<<<g2, 256>>>(Wf);

    softmax_v5<<<N_ROWS / 4, 128>>>(alpha);

    dim3 g4(E_DIM / 32, N_ROWS / 64);
    tc_gemm_ab<<<g4, 128>>>(awe);
}